// round 3
// baseline (speedup 1.0000x reference)
#include <cuda_runtime.h>

// Problem: B=32, T=256, D=64.
// real, imag: [B, T, D] float32.
// out: [2, T, B, D, D] float32.
//   out_real[t,b,p,q] = r_p*r_q + i_p*i_q
//   out_imag[t,b,p,q] = i_p*r_q - r_p*i_q
// where r = real[b, t, :], i = imag[b, t, :].

#define PB 32
#define PT 256
#define PD 64
#define TILE (PD * PD)            // 4096 floats per (t,b) per component
#define IMAG_OFF ((size_t)PT * PB * TILE)

// 256-bit streaming store (sm_100+): one STG.256, warp covers 1KiB contiguous.
__device__ __forceinline__ void st256_cs(float* ptr,
                                         float v0, float v1, float v2, float v3,
                                         float v4, float v5, float v6, float v7)
{
    asm volatile("st.global.cs.v8.f32 [%0], {%1,%2,%3,%4,%5,%6,%7,%8};"
                 :: "l"(ptr),
                    "f"(v0), "f"(v1), "f"(v2), "f"(v3),
                    "f"(v4), "f"(v5), "f"(v6), "f"(v7)
                 : "memory");
}

__global__ __launch_bounds__(256, 6)
void qouterc_kernel(const float* __restrict__ real,
                    const float* __restrict__ imag,
                    float* __restrict__ out)
{
    const int tb = blockIdx.x;          // tb = t*B + b  (matches out layout)
    const int t  = tb >> 5;             // / 32
    const int b  = tb & 31;

    __shared__ float rs[PD];
    __shared__ float is[PD];

    const int tid = threadIdx.x;

    // Input layout [B, T, D]: element (b, t, d) at b*T*D + t*D + d
    const size_t in_base = (size_t)b * (PT * PD) + (size_t)t * PD;
    if (tid < PD)
        rs[tid] = real[in_base + tid];
    else if (tid < 2 * PD)
        is[tid - PD] = imag[in_base + (tid - PD)];
    __syncthreads();

    // Output tile for this (t,b): 4096 floats = 512 float8 per component.
    // Thread mapping: float8 index n8 = j*256 + tid (j = 0..1)
    //   -> p = n8 / 8 (row), q = (n8 % 8) * 8 (starting column)
    //   -> each warp STG.256 covers a contiguous 1KiB span.
    // Tile base is 16KiB-aligned -> every float8 address is 32B-aligned.
    float* out_r = out + (size_t)tb * TILE;
    float* out_i = out + IMAG_OFF + (size_t)tb * TILE;

    #pragma unroll
    for (int j = 0; j < 2; ++j) {
        const int n8 = j * 256 + tid;       // float8 index within tile, 0..511
        const int p  = n8 >> 3;             // row
        const int q  = (n8 & 7) << 3;       // starting column

        const float rp = rs[p];
        const float ip = is[p];

        float rq[8], iq[8];
        #pragma unroll
        for (int k = 0; k < 8; ++k) { rq[k] = rs[q + k]; iq[k] = is[q + k]; }

        // Real part: rp*rq + ip*iq
        st256_cs(out_r + ((size_t)n8 << 3),
                 rp * rq[0] + ip * iq[0], rp * rq[1] + ip * iq[1],
                 rp * rq[2] + ip * iq[2], rp * rq[3] + ip * iq[3],
                 rp * rq[4] + ip * iq[4], rp * rq[5] + ip * iq[5],
                 rp * rq[6] + ip * iq[6], rp * rq[7] + ip * iq[7]);

        // Imag part: ip*rq - rp*iq
        st256_cs(out_i + ((size_t)n8 << 3),
                 ip * rq[0] - rp * iq[0], ip * rq[1] - rp * iq[1],
                 ip * rq[2] - rp * iq[2], ip * rq[3] - rp * iq[3],
                 ip * rq[4] - rp * iq[4], ip * rq[5] - rp * iq[5],
                 ip * rq[6] - rp * iq[6], ip * rq[7] - rp * iq[7]);
    }
}

extern "C" void kernel_launch(void* const* d_in, const int* in_sizes, int n_in,
                              void* d_out, int out_size)
{
    const float* real = (const float*)d_in[0];
    const float* imag = (const float*)d_in[1];
    float* out = (float*)d_out;

    // One CTA per (t, b) pair: T*B = 8192 CTAs, 256 threads each.
    qouterc_kernel<<<PT * PB, 256>>>(real, imag, out);
}

// round 5
// speedup vs baseline: 1.1102x; 1.1102x over previous
#include <cuda_runtime.h>

// Problem: B=32, T=256, D=64.
// real, imag: [B, T, D] float32.
// out: [2, T, B, D, D] float32.
//   out_real[t,b,p,q] = r_p*r_q + i_p*i_q
//   out_imag[t,b,p,q] = i_p*r_q - r_p*i_q
// where r = real[b, t, :], i = imag[b, t, :].

#define PB 32
#define PT 256
#define PD 64
#define TILE (PD * PD)            // 4096 floats per (t,b) per component
#define NTB  (PT * PB)            // 8192 tiles per component
#define IMAG_OFF ((size_t)NTB * TILE)

__global__ __launch_bounds__(256, 8)
void qouterc_kernel(const float* __restrict__ real,
                    const float* __restrict__ imag,
                    float* __restrict__ out)
{
    // grid = 2 * NTB. First NTB CTAs write the real half, next NTB the imag
    // half. Each CTA writes exactly ONE contiguous 16KiB output stream.
    const int bid  = blockIdx.x;
    const int comp = bid >> 13;         // 0 = real part, 1 = imag part
    const int tb   = bid & (NTB - 1);   // tb = t*B + b (matches out layout)
    const int t    = tb >> 5;           // / 32
    const int b    = tb & 31;

    __shared__ float rs[PD];
    __shared__ float is[PD];

    const int tid = threadIdx.x;

    // Input layout [B, T, D]: element (b, t, d) at b*T*D + t*D + d
    const size_t in_base = (size_t)b * (PT * PD) + (size_t)t * PD;
    if (tid < PD)
        rs[tid] = real[in_base + tid];
    else if (tid < 2 * PD)
        is[tid - PD] = imag[in_base + (tid - PD)];
    __syncthreads();

    // Output tile: 4096 floats = 1024 float4.
    // float4 index n4 = j*256 + tid -> each warp STG.128 covers a contiguous
    // 512B span; CTA's full write stream is a single contiguous 16KiB run.
    float* out_t = out + (size_t)comp * IMAG_OFF + (size_t)tb * TILE;

    #pragma unroll
    for (int j = 0; j < 4; ++j) {
        const int n4 = j * 256 + tid;       // 0..1023
        const int p  = n4 >> 4;             // row (16 float4 per 64-col row)
        const int q  = (n4 & 15) << 2;      // starting column

        const float rp = rs[p];
        const float ip = is[p];

        float4 v;
        if (comp == 0) {
            v.x = rp * rs[q + 0] + ip * is[q + 0];
            v.y = rp * rs[q + 1] + ip * is[q + 1];
            v.z = rp * rs[q + 2] + ip * is[q + 2];
            v.w = rp * rs[q + 3] + ip * is[q + 3];
        } else {
            v.x = ip * rs[q + 0] - rp * is[q + 0];
            v.y = ip * rs[q + 1] - rp * is[q + 1];
            v.z = ip * rs[q + 2] - rp * is[q + 2];
            v.w = ip * rs[q + 3] - rp * is[q + 3];
        }

        // Streaming store: 256MiB write-once output, evict-first in L2.
        __stcs(reinterpret_cast<float4*>(out_t) + n4, v);
    }
}

extern "C" void kernel_launch(void* const* d_in, const int* in_sizes, int n_in,
                              void* d_out, int out_size)
{
    const float* real = (const float*)d_in[0];
    const float* imag = (const float*)d_in[1];
    float* out = (float*)d_out;

    // 2 components x 8192 (t,b) tiles; 256 threads each.
    qouterc_kernel<<<2 * NTB, 256>>>(real, imag, out);
}

// round 6
// speedup vs baseline: 1.1280x; 1.0160x over previous
#include <cuda_runtime.h>

// Problem: B=32, T=256, D=64.
// real, imag: [B, T, D] float32.
// out: [2, T, B, D, D] float32.
//   out_real[t,b,p,q] = r_p*r_q + i_p*i_q
//   out_imag[t,b,p,q] = i_p*r_q - r_p*i_q
// where r = real[b, t, :], i = imag[b, t, :].

#define PB 32
#define PT 256
#define PD 64
#define TILE (PD * PD)            // 4096 floats per (t,b) per component
#define NTB  (PT * PB)            // 8192 tiles per component
#define IMAG_OFF ((size_t)NTB * TILE)

__global__ __launch_bounds__(256, 8)
void qouterc_kernel(const float* __restrict__ real,
                    const float* __restrict__ imag,
                    float* __restrict__ out)
{
    // grid = 2 * NTB. First NTB CTAs write the real half, next NTB the imag
    // half. Each CTA writes exactly ONE contiguous 16KiB output stream.
    const int bid  = blockIdx.x;
    const int comp = bid >> 13;         // 0 = real part, 1 = imag part
    const int tb   = bid & (NTB - 1);   // tb = t*B + b (matches out layout)
    const int t    = tb >> 5;           // / 32
    const int b    = tb & 31;

    __shared__ __align__(16) float rs[PD];
    __shared__ __align__(16) float is[PD];

    const int tid = threadIdx.x;

    // Input layout [B, T, D]: element (b, t, d) at b*T*D + t*D + d
    const size_t in_base = (size_t)b * (PT * PD) + (size_t)t * PD;
    if (tid < PD)
        rs[tid] = real[in_base + tid];
    else if (tid < 2 * PD)
        is[tid - PD] = imag[in_base + (tid - PD)];
    __syncthreads();

    // Mapping: n4 = j*256 + tid, p = n4>>4 = j*16 + (tid>>4),
    //          q = (n4&15)<<2 = (tid&15)<<2  -> q is j-INVARIANT.
    // So the 4 q-values are loaded ONCE as a single LDS.128 pair and reused
    // across all 4 j iterations. Per-thread LDS: 2x LDS.128 + 8 broadcast
    // scalars (was ~40 scalar LDS) -> ~4x less L1 shared traffic.
    const int q  = (tid & 15) << 2;
    const int p0 = tid >> 4;

    const float4 rq4 = *reinterpret_cast<const float4*>(&rs[q]);
    const float4 iq4 = *reinterpret_cast<const float4*>(&is[q]);

    float* out_t = out + (size_t)comp * IMAG_OFF + (size_t)tb * TILE;

    #pragma unroll
    for (int j = 0; j < 4; ++j) {
        const int p  = j * 16 + p0;          // row
        const int n4 = j * 256 + tid;        // float4 index, 0..1023

        const float rp = rs[p];              // broadcast LDS (conflict-free)
        const float ip = is[p];

        float4 v;
        if (comp == 0) {
            v.x = rp * rq4.x + ip * iq4.x;
            v.y = rp * rq4.y + ip * iq4.y;
            v.z = rp * rq4.z + ip * iq4.z;
            v.w = rp * rq4.w + ip * iq4.w;
        } else {
            v.x = ip * rq4.x - rp * iq4.x;
            v.y = ip * rq4.y - rp * iq4.y;
            v.z = ip * rq4.z - rp * iq4.z;
            v.w = ip * rq4.w - rp * iq4.w;
        }

        // Streaming store: 256MiB write-once output, evict-first in L2.
        __stcs(reinterpret_cast<float4*>(out_t) + n4, v);
    }
}

extern "C" void kernel_launch(void* const* d_in, const int* in_sizes, int n_in,
                              void* d_out, int out_size)
{
    const float* real = (const float*)d_in[0];
    const float* imag = (const float*)d_in[1];
    float* out = (float*)d_out;

    // 2 components x 8192 (t,b) tiles; 256 threads each.
    qouterc_kernel<<<2 * NTB, 256>>>(real, imag, out);
}